// round 15
// baseline (speedup 1.0000x reference)
#include <cuda_runtime.h>

#define NB 4
#define NC 21
#define HH 512
#define WW 512
#define PH 171
#define OH 169
#define NCCH 84
#define PP (PH*PH)
#define LLN (OH*OH)
#define SRW 176
#define RB2 25
#define NBAND 7
#define ALPHA 5e-4f

__device__ float    g_pr[NCCH*PP];      // pooled clipped sigmoid − 0.5
__device__ unsigned g_lab[NB*PP];
__device__ float    g_Tpart[NCCH*NBAND*64];
__device__ float    g_Tred[NCCH*64];
__device__ float    g_frame[NCCH*192];
__device__ float    g_ce[NB*PH];
__device__ int      g_cnt[NB*PH];

__device__ __forceinline__ float ftanh(float x){float r;asm("tanh.approx.f32 %0,%1;":"=f"(r):"f"(x));return r;}

// ============ K1: CE + raw-score maxpool + sigmoid-after-pool + label bits ==
__global__ __launch_bounds__(512) void k_fused(const float* __restrict__ score,
                                               const int*   __restrict__ tg)
{
    __shared__ float    spx[NC*WW];
    __shared__ unsigned slab[WW];
    __shared__ float wce[16];
    __shared__ int   wcnt[16];
    __shared__ int   s_is64;

    const int oy = blockIdx.x, n = blockIdx.y, x = threadIdx.x;

    if (x == 0) {
        int is64 = 1;
        #pragma unroll
        for (int i = 0; i < 32; i++) if (tg[2*i+1] != 0) is64 = 0;
        s_is64 = is64;
    }
    __syncthreads();
    const bool is64 = (s_is64 != 0);
    const long long* tg64 = (const long long*)tg;

    float vpool[NC];
    #pragma unroll
    for (int cc = 0; cc < NC; cc++) vpool[cc] = -1e30f;
    unsigned labbits = 0;
    float ce = 0.0f; int cnt = 0;

    const int r0 = 3*oy - 1;
    #pragma unroll
    for (int k = 0; k < 3; k++) {
        int r = r0 + k;
        if (r < 0 || r >= HH) continue;
        int pix = (n*HH + r)*WW + x;
        int t = is64 ? (int)tg64[pix] : tg[pix];
        bool mask21 = (t >= 0 && t < NC);
        bool valid  = (t != 255);
        const float* bp = score + ((size_t)(n*NC)*HH + r)*WW + x;

        float s0 = 0.f, s1 = 0.f, s2 = 0.f, xt = 0.f;
        #pragma unroll
        for (int cc = 0; cc < NC; cc++) {
            float v = __ldg(bp + (size_t)cc*(HH*WW));
            float e = __expf(v);
            if (cc % 3 == 0) s0 += e; else if (cc % 3 == 1) s1 += e; else s2 += e;
            if (cc == t) xt = v;
            float vm = mask21 ? v : -1e30f;
            vpool[cc] = fmaxf(vpool[cc], vm);
        }
        if (valid) { ce += __logf((s0 + s1) + s2) - xt; cnt++; }
        if (mask21) labbits |= (1u << t);
    }

    #pragma unroll
    for (int cc = 0; cc < NC; cc++) spx[cc*WW + x] = vpool[cc];
    slab[x] = labbits;

    #pragma unroll
    for (int o = 16; o; o >>= 1) {
        ce  += __shfl_xor_sync(0xffffffffu, ce, o);
        cnt += __shfl_xor_sync(0xffffffffu, cnt, o);
    }
    if ((x & 31) == 0) { wce[x >> 5] = ce; wcnt[x >> 5] = cnt; }
    __syncthreads();
    if (x == 0) {
        float s = 0.f; int cc2 = 0;
        #pragma unroll
        for (int i = 0; i < 16; i++) { s += wce[i]; cc2 += wcnt[i]; }
        g_ce[n*PH + oy] = s; g_cnt[n*PH + oy] = cc2;
    }

    for (int idx = x; idx < NC*PH; idx += 512) {
        int c = idx / PH, ox = idx - c*PH;
        int c0 = 3*ox - 1;
        float pm = -1e30f; unsigned ob = 0;
        #pragma unroll
        for (int j = 0; j < 3; j++) {
            int cc = c0 + j;
            if (cc >= 0 && cc < WW) { pm = fmaxf(pm, spx[c*WW + cc]); ob |= slab[cc]; }
        }
        float sg  = fmaf(ftanh(0.5f*pm), 0.5f, 0.5f);
        float val = fminf(fmaxf(sg, 1e-6f), 1.0f) - 0.5f;
        g_pr[((n*NC + c)*PH + oy)*PH + ox] = val;
        if (c == 0) g_lab[(n*PH + oy)*PH + ox] = ob;
    }
}

// ============ K2: full-plane correlations (zero-padded), 25+13+13+2 accs ===
// group A (128 thr): acc[0..24] = T_lp(dy,dx) at (dy+2)*5+(dx+2); [25]=SumL; [26]=SumP
// group B (128 thr): acc[0..12] = T_pp canonical; acc[13..25] = T_ll canonical
__global__ __launch_bounds__(256, 3) void k_mom2()
{
    __shared__ float sp[29*SRW];
    __shared__ float sl[29*SRW];
    __shared__ float wbuf[8][27];

    const int nc = blockIdx.x, band = blockIdx.y;
    const int n = nc / NC, c = nc - n*NC;
    const int tid = threadIdx.x;
    const int r0 = band*RB2;

    // stage rows r0-2 .. r0+26, plane col x at smem col x+2, zero-padded
    for (int i = tid; i < 29*SRW; i += 256) {
        int r = i / SRW, xs = i - r*SRW;
        int gr = r0 - 2 + r, gx = xs - 2;
        float pv = 0.f, lv = 0.f;
        if (gr >= 0 && gr < PH && gx >= 0 && gx < PH) {
            int gi = gr*PH + gx;
            pv = g_pr[nc*PP + gi];
            lv = ((g_lab[n*PP + gi] >> c) & 1u) ? 0.5f : -0.5f;
        }
        sp[i] = pv; sl[i] = lv;
    }
    __syncthreads();

    const int grp = tid >> 7;
    const int gt  = tid & 127;
    const int warp = tid >> 5, lane = tid & 31;

    float acc[27];
    #pragma unroll
    for (int i = 0; i < 27; i++) acc[i] = 0.f;

    const int tr  = gt / 5;            // local row 0..24
    const int seg = gt - tr*5;
    const bool act = (gt < 125) && (r0 + tr < PH);

    if (act) {
        const int vs = seg*35;
        const int ve = min(vs + 35, PH);

        if (grp == 0) {
            float Pw[5][5];
            #pragma unroll
            for (int k = 0; k < 5; k++) {
                const float* rp = sp + (tr + k)*SRW;
                Pw[k][3] = rp[vs+0]; Pw[k][4] = rp[vs+1];
                Pw[k][0] = rp[vs+2]; Pw[k][1] = rp[vs+3];
                Pw[k][2] = 0.f;
            }
            const float* lrow = sl + (tr + 2)*SRW;
            for (int m = 0; m < 7; m++) {
                #pragma unroll
                for (int j = 0; j < 5; j++) {
                    int vv = vs + m*5 + j;
                    if (vv < ve) {
                        #pragma unroll
                        for (int k = 0; k < 5; k++)
                            Pw[k][(j+2)%5] = sp[(tr + k)*SRW + vv + 4];
                        float lc = lrow[vv + 2];
                        #pragma unroll
                        for (int ky = 0; ky < 5; ky++)
                            #pragma unroll
                            for (int kx = 0; kx < 5; kx++)
                                acc[ky*5+kx] = fmaf(lc, Pw[ky][(j+kx+3)%5], acc[ky*5+kx]);
                        acc[25] += lc;
                        acc[26] += Pw[2][j%5];
                    }
                }
            }
        } else {
            float Pw[3][5], Lw[3][5];
            #pragma unroll
            for (int k = 0; k < 3; k++) {
                const float* rp = sp + (tr + 2 + k)*SRW;
                const float* rl = sl + (tr + 2 + k)*SRW;
                Pw[k][3] = rp[vs+0]; Pw[k][4] = rp[vs+1];
                Pw[k][0] = rp[vs+2]; Pw[k][1] = rp[vs+3]; Pw[k][2] = 0.f;
                Lw[k][3] = rl[vs+0]; Lw[k][4] = rl[vs+1];
                Lw[k][0] = rl[vs+2]; Lw[k][1] = rl[vs+3]; Lw[k][2] = 0.f;
            }
            for (int m = 0; m < 7; m++) {
                #pragma unroll
                for (int j = 0; j < 5; j++) {
                    int vv = vs + m*5 + j;
                    if (vv < ve) {
                        #pragma unroll
                        for (int k = 0; k < 3; k++) {
                            Pw[k][(j+2)%5] = sp[(tr + 2 + k)*SRW + vv + 4];
                            Lw[k][(j+2)%5] = sl[(tr + 2 + k)*SRW + vv + 4];
                        }
                        float pc = Pw[0][j%5], lc = Lw[0][j%5];
                        #pragma unroll
                        for (int dx = 0; dx < 3; dx++) {
                            acc[dx]    = fmaf(pc, Pw[0][(j+dx)%5], acc[dx]);
                            acc[13+dx] = fmaf(lc, Lw[0][(j+dx)%5], acc[13+dx]);
                        }
                        #pragma unroll
                        for (int dy = 1; dy < 3; dy++)
                            #pragma unroll
                            for (int dx = -2; dx <= 2; dx++) {
                                int ii = dy*5 + dx;    // 3..7 / 8..12
                                acc[ii]    = fmaf(pc, Pw[dy][(j+dx+5)%5], acc[ii]);
                                acc[13+ii] = fmaf(lc, Lw[dy][(j+dx+5)%5], acc[13+ii]);
                            }
                    }
                }
            }
        }
    }

    #pragma unroll
    for (int j = 0; j < 27; j++) {
        float v = acc[j];
        #pragma unroll
        for (int o = 16; o; o >>= 1) v += __shfl_xor_sync(0xffffffffu, v, o);
        if (lane == (j & 31)) wbuf[warp][j] = v;
    }
    __syncthreads();

    if (tid < 27) {
        float s = wbuf[0][tid] + wbuf[1][tid] + wbuf[2][tid] + wbuf[3][tid];
        g_Tpart[(nc*NBAND + band)*64 + tid] = s;
    } else if (tid >= 32 && tid < 58) {
        int j = tid - 32;
        float s = wbuf[4][j] + wbuf[5][j] + wbuf[6][j] + wbuf[7][j];
        g_Tpart[(nc*NBAND + band)*64 + tid] = s;
    }
}

// ============ k_corr: boundary frames, one thread per pair =================
// t<81: lp frame (d=la,e=pr); 81..125: pp tri; 126..134: s_pr; 135..179: ll tri; 180..188: s_la
__global__ __launch_bounds__(192) void k_corr()
{
    const int nc = blockIdx.x;
    const int n = nc / NC, c = nc - n*NC;
    const int t = threadIdx.x;
    if (t >= 189) return;

    const float*    P  = g_pr + nc*PP;
    const unsigned* Lb = g_lab + n*PP;

    int mode, d = 0, e = 0;
    if (t < 81)       { mode = 0; d = t/9; e = t%9; }
    else if (t < 126) { mode = 1; int k = t-81;  while (k >= 9-d) { k -= 9-d; d++; } e = d+k; }
    else if (t < 135) { mode = 2; d = t-126; }
    else if (t < 180) { mode = 3; int k = t-135; while (k >= 9-d) { k -= 9-d; d++; } e = d+k; }
    else              { mode = 4; d = t-180; }

    const int yd = d/3, xd = d%3;
    int dy = 0, dx = 0;
    if (mode == 0 || mode == 1 || mode == 3) { dy = e/3 - yd; dx = e%3 - xd; }

    float acc = 0.f;
    for (int u = 0; u < PH; u++) {
        int y2 = u + dy;
        bool yok = (y2 >= 0 && y2 < PH);
        bool inrow = (u >= yd) && (u < yd + OH);
        int vA1 = inrow ? xd : PH;
        int vB0 = inrow ? xd + OH : PH;
        #pragma unroll 1
        for (int pass = 0; pass < 2; pass++) {
            int v0 = pass ? vB0 : 0;
            int v1 = pass ? PH  : vA1;
            for (int v = v0; v < v1; v++) {
                float a = (mode == 1 || mode == 2) ? P[u*PH + v]
                          : (((Lb[u*PH + v] >> c) & 1u) ? 0.5f : -0.5f);
                float b;
                if (mode == 2 || mode == 4) b = 1.f;
                else {
                    int x2 = v + dx;
                    bool ok = yok && (x2 >= 0) && (x2 < PH);
                    if (mode == 3) b = ok ? (((Lb[y2*PH + x2] >> c) & 1u) ? 0.5f : -0.5f) : 0.f;
                    else           b = ok ? P[y2*PH + x2] : 0.f;
                }
                acc = fmaf(a, b, acc);
            }
        }
    }
    g_frame[nc*192 + t] = acc;
}

// ============ K3: reduce + assemble S + 9x9 linear algebra =================
#define TRI(d,e) ((d)*9 - (d)*((d)-1)/2 + (e)-(d))

__global__ __launch_bounds__(256) void k_final(float* __restrict__ out, int out_size)
{
    __shared__ float srmi[NCCH];
    __shared__ float rce[256];
    __shared__ int   rcn[256];
    const int tid = threadIdx.x;

    for (int i = tid; i < NCCH*64; i += 256) {
        int nc = i >> 6, j = i & 63;
        float s = 0.f;
        #pragma unroll
        for (int b = 0; b < NBAND; b++) s += g_Tpart[(nc*NBAND + b)*64 + j];
        g_Tred[nc*64 + j] = s;
    }

    float cs = 0.f; int cc = 0;
    for (int i = tid; i < NB*PH; i += 256) { cs += g_ce[i]; cc += g_cnt[i]; }
    rce[tid] = cs; rcn[tid] = cc;
    __syncthreads();
    for (int o = 128; o; o >>= 1) {
        if (tid < o) { rce[tid] += rce[tid+o]; rcn[tid] += rcn[tid+o]; }
        __syncthreads();
    }

    if (tid < NCCH) {
        const float* T  = g_Tred  + tid*64;
        const float* fr = g_frame + tid*192;
        const float invL = 1.0f / (float)LLN;
        float clp[81], cpp[45], cll[45], spr[9], sla[9];
        #pragma unroll
        for (int d = 0; d < 9; d++) {
            spr[d] = T[26] - fr[126+d];
            sla[d] = T[25] - fr[180+d];
        }
        int k = 0;
        for (int d = 0; d < 9; d++)
            for (int e = d; e < 9; e++) {
                int dy = e/3 - d/3, dx = e%3 - d%3;
                int pi = (dy == 0) ? dx : (dy == 1 ? 5+dx : 10+dx);
                float Spp = T[32+pi] - fr[81+k];
                float Sll = T[45+pi] - fr[135+k];
                cpp[k] = Spp - spr[d]*spr[e]*invL + (d==e ? ALPHA : 0.0f);
                cll[k] = Sll - sla[d]*sla[e]*invL;
                k++;
            }
        for (int d = 0; d < 9; d++)
            for (int e = 0; e < 9; e++) {
                int dy = e/3 - d/3, dx = e%3 - d%3;
                int a = (dy+2)*5 + (dx+2);
                clp[d*9+e] = (T[a] - fr[d*9+e]) - sla[d]*spr[e]*invL;
            }

        for (int j = 0; j < 9; j++) {
            float s = cpp[TRI(j,j)];
            for (int q = 0; q < j; q++) { float g = cpp[TRI(q,j)]; s -= g*g; }
            float gjj = sqrtf(fmaxf(s, 1e-20f));
            cpp[TRI(j,j)] = gjj;
            float inv = 1.0f / gjj;
            for (int i = j+1; i < 9; i++) {
                float t = cpp[TRI(j,i)];
                for (int q = 0; q < j; q++) t -= cpp[TRI(q,i)]*cpp[TRI(q,j)];
                cpp[TRI(j,i)] = t*inv;
            }
        }
        for (int d = 0; d < 9; d++)
            for (int i = 0; i < 9; i++) {
                float s = clp[d*9+i];
                for (int q = 0; q < i; q++) s -= cpp[TRI(q,i)]*clp[d*9+q];
                clp[d*9+i] = s / cpp[TRI(i,i)];
            }
        k = 0;
        for (int d = 0; d < 9; d++)
            for (int e = d; e < 9; e++) {
                float s = cll[k];
                for (int i = 0; i < 9; i++) s -= clp[d*9+i]*clp[e*9+i];
                if (d == e) s += ALPHA;
                cll[k] = s; k++;
            }
        float rmi = 0.0f;
        for (int j = 0; j < 9; j++) {
            float s = cll[TRI(j,j)];
            for (int q = 0; q < j; q++) { float g = cll[TRI(q,j)]; s -= g*g; }
            float gjj = sqrtf(fmaxf(s, 0.0f));
            cll[TRI(j,j)] = gjj;
            float inv = 1.0f / gjj;
            for (int i = j+1; i < 9; i++) {
                float t = cll[TRI(j,i)];
                for (int q = 0; q < j; q++) t -= cll[TRI(q,i)]*cll[TRI(q,j)];
                cll[TRI(j,i)] = t*inv;
            }
            rmi += logf(gjj + 1e-8f);
        }
        srmi[tid] = rmi;
    }
    __syncthreads();

    if (tid == 0) {
        float rs = 0.f;
        #pragma unroll
        for (int i = 0; i < NCCH; i++) rs += srmi[i];
        float normal = rce[0] / (float)rcn[0];
        float loss = 0.5f*normal + 0.5f*(rs / 36.0f);
        for (int i = 0; i < out_size; i++) out[i] = loss;
    }
}

extern "C" void kernel_launch(void* const* d_in, const int* in_sizes, int n_in,
                              void* d_out, int out_size)
{
    const float* score;
    const int*   tg;
    if (in_sizes[0] >= in_sizes[1]) { score = (const float*)d_in[0]; tg = (const int*)d_in[1]; }
    else                            { score = (const float*)d_in[1]; tg = (const int*)d_in[0]; }

    k_fused<<<dim3(PH, NB), 512>>>(score, tg);
    k_mom2<<<dim3(NCCH, NBAND), 256>>>();
    k_corr<<<NCCH, 192>>>();
    k_final<<<1, 256>>>((float*)d_out, out_size);
}

// round 16
// speedup vs baseline: 3.6437x; 3.6437x over previous
#include <cuda_runtime.h>

#define NB 4
#define NC 21
#define HH 512
#define WW 512
#define PH 171
#define OH 169
#define NCCH 84
#define PP (PH*PH)
#define LLN (OH*OH)
#define SRW 176
#define RB 27
#define BD2 7
#define MSZ 192
#define ALPHA 5e-4f

__device__ float    g_pr[NCCH*PP];      // pooled clipped sigmoid − 0.5
__device__ unsigned g_lab[NB*PP];
__device__ float    g_mpart[NCCH*BD2*MSZ];
__device__ float    g_rmi[NCCH];
__device__ float    g_ce[NB*PH];
__device__ int      g_cnt[NB*PH];

__device__ __forceinline__ float ftanh(float x){float r;asm("tanh.approx.f32 %0,%1;":"=f"(r):"f"(x));return r;}

// ============ K1: CE + raw-score maxpool + sigmoid-after-pool + label bits ==
__global__ __launch_bounds__(512) void k_fused(const float* __restrict__ score,
                                               const int*   __restrict__ tg)
{
    __shared__ float    spx[NC*WW];
    __shared__ unsigned slab[WW];
    __shared__ float wce[16];
    __shared__ int   wcnt[16];
    __shared__ int   s_is64;

    const int oy = blockIdx.x, n = blockIdx.y, x = threadIdx.x;

    if (x == 0) {
        int is64 = 1;
        #pragma unroll
        for (int i = 0; i < 32; i++) if (tg[2*i+1] != 0) is64 = 0;
        s_is64 = is64;
    }
    __syncthreads();
    const bool is64 = (s_is64 != 0);
    const long long* tg64 = (const long long*)tg;

    float vpool[NC];
    #pragma unroll
    for (int cc = 0; cc < NC; cc++) vpool[cc] = -1e30f;
    unsigned labbits = 0;
    float ce = 0.0f; int cnt = 0;

    const int r0 = 3*oy - 1;
    #pragma unroll
    for (int k = 0; k < 3; k++) {
        int r = r0 + k;
        if (r < 0 || r >= HH) continue;
        int pix = (n*HH + r)*WW + x;
        int t = is64 ? (int)tg64[pix] : tg[pix];
        bool mask21 = (t >= 0 && t < NC);
        bool valid  = (t != 255);
        const float* bp = score + ((size_t)(n*NC)*HH + r)*WW + x;

        float s0 = 0.f, s1 = 0.f, s2 = 0.f, xt = 0.f;
        #pragma unroll
        for (int cc = 0; cc < NC; cc++) {
            float v = __ldg(bp + (size_t)cc*(HH*WW));
            float e = __expf(v);
            if (cc % 3 == 0) s0 += e; else if (cc % 3 == 1) s1 += e; else s2 += e;
            if (cc == t) xt = v;
            float vm = mask21 ? v : -1e30f;
            vpool[cc] = fmaxf(vpool[cc], vm);
        }
        if (valid) { ce += __logf((s0 + s1) + s2) - xt; cnt++; }
        if (mask21) labbits |= (1u << t);
    }

    #pragma unroll
    for (int cc = 0; cc < NC; cc++) spx[cc*WW + x] = vpool[cc];
    slab[x] = labbits;

    #pragma unroll
    for (int o = 16; o; o >>= 1) {
        ce  += __shfl_xor_sync(0xffffffffu, ce, o);
        cnt += __shfl_xor_sync(0xffffffffu, cnt, o);
    }
    if ((x & 31) == 0) { wce[x >> 5] = ce; wcnt[x >> 5] = cnt; }
    __syncthreads();
    if (x == 0) {
        float s = 0.f; int cc2 = 0;
        #pragma unroll
        for (int i = 0; i < 16; i++) { s += wce[i]; cc2 += wcnt[i]; }
        g_ce[n*PH + oy] = s; g_cnt[n*PH + oy] = cc2;
    }

    for (int idx = x; idx < NC*PH; idx += 512) {
        int c = idx / PH, ox = idx - c*PH;
        int c0 = 3*ox - 1;
        float pm = -1e30f; unsigned ob = 0;
        #pragma unroll
        for (int j = 0; j < 3; j++) {
            int cc = c0 + j;
            if (cc >= 0 && cc < WW) { pm = fmaxf(pm, spx[c*WW + cc]); ob |= slab[cc]; }
        }
        float sg  = fmaf(ftanh(0.5f*pm), 0.5f, 0.5f);
        float val = fminf(fmaxf(sg, 1e-6f), 1.0f) - 0.5f;
        g_pr[((n*NC + c)*PH + oy)*PH + ox] = val;
        if (c == 0) g_lab[(n*PH + oy)*PH + ox] = ob;
    }
}

// ============ K2: Gram moments, 5 groups x 64 thr, scalar FFMA =============
#define TRI(d,e) ((d)*9 - (d)*((d)-1)/2 + (e)-(d))

__device__ __forceinline__ void load8(const float* p, float* a)
{
    float4 u0 = *(const float4*)p;
    float4 u1 = *(const float4*)(p + 4);
    a[0]=u0.x; a[1]=u0.y; a[2]=u0.z; a[3]=u0.w;
    a[4]=u1.x; a[5]=u1.y; a[6]=u1.z; a[7]=u1.w;
}

__global__ __launch_bounds__(320, 2) void k_mom()
{
    __shared__ float sp[29*SRW];
    __shared__ float sl[29*SRW];
    __shared__ float wbuf[10][54];

    const int nc = blockIdx.x, band = blockIdx.y;
    const int n = nc / NC, c = nc - n*NC;
    const int tid = threadIdx.x;
    const int r0 = band*RB;
    const int rows_out = min(RB, OH - r0);
    const int nin = rows_out + 2;

    for (int i = tid; i < 29*SRW; i += 320) {
        int r = i / SRW, x = i - r*SRW;
        float pv = 0.f, lv = 0.f;
        if (r < nin && x < PH) {
            int gi = (r0 + r)*PH + x;
            pv = g_pr[nc*PP + gi];
            lv = ((g_lab[n*PP + gi] >> c) & 1u) ? 0.5f : -0.5f;
        }
        sp[i] = pv; sl[i] = lv;
    }
    __syncthreads();

    const int grp = tid >> 6;         // 0,1,2 = lp dy; 3 = pp; 4 = ll
    const int gt  = tid & 63;
    const int warp = tid >> 5, lane = tid & 31;
    const int nq = rows_out*43;

    if (grp < 3) {
        const int dy = grp;
        float acc[27];
        #pragma unroll
        for (int i = 0; i < 27; i++) acc[i] = 0.f;

        int row = (gt >= 43) ? 1 : 0;
        int qx  = gt - (row ? 43 : 0);
        for (int q = gt; q < nq; q += 64) {
            const int xq = qx*4;
            float A[8], B[3][8];
            load8(sl + (row+dy)*SRW + xq, A);
            #pragma unroll
            for (int ey = 0; ey < 3; ey++) load8(sp + (row+ey)*SRW + xq, B[ey]);
            const int nv = 169 - xq;
            #pragma unroll
            for (int q2 = 0; q2 < 4; q2++) {
                if (q2 < nv) {
                    #pragma unroll
                    for (int dx = 0; dx < 3; dx++) {
                        float l = A[q2+dx];
                        #pragma unroll
                        for (int e = 0; e < 9; e++)
                            acc[dx*9+e] = fmaf(l, B[e/3][q2 + e%3], acc[dx*9+e]);
                    }
                }
            }
            qx += 21; row += 1;
            if (qx >= 43) { qx -= 43; row += 1; }
        }
        #pragma unroll
        for (int j = 0; j < 27; j++) {
            float v = acc[j];
            #pragma unroll
            for (int o = 16; o; o >>= 1) v += __shfl_xor_sync(0xffffffffu, v, o);
            if (lane == (j & 31)) wbuf[warp][j] = v;
        }
    } else {
        const float* S = (grp == 3) ? sp : sl;
        float accT[45], accS[9];
        #pragma unroll
        for (int i = 0; i < 45; i++) accT[i] = 0.f;
        #pragma unroll
        for (int i = 0; i < 9; i++) accS[i] = 0.f;

        int row = (gt >= 43) ? 1 : 0;
        int qx  = gt - (row ? 43 : 0);
        for (int q = gt; q < nq; q += 64) {
            const int xq = qx*4;
            float B[3][8];
            #pragma unroll
            for (int y = 0; y < 3; y++) load8(S + (row+y)*SRW + xq, B[y]);
            const int nv = 169 - xq;
            #pragma unroll
            for (int q2 = 0; q2 < 4; q2++) {
                if (q2 < nv) {
                    float v[9];
                    #pragma unroll
                    for (int d = 0; d < 9; d++) v[d] = B[d/3][q2 + d%3];
                    int k = 0;
                    #pragma unroll
                    for (int d = 0; d < 9; d++) {
                        accS[d] += v[d];
                        #pragma unroll
                        for (int e = d; e < 9; e++) { accT[k] = fmaf(v[d], v[e], accT[k]); k++; }
                    }
                }
            }
            qx += 21; row += 1;
            if (qx >= 43) { qx -= 43; row += 1; }
        }
        float red[54];
        #pragma unroll
        for (int k = 0; k < 45; k++) red[k] = accT[k];
        #pragma unroll
        for (int d = 0; d < 9; d++) red[45+d] = accS[d];
        #pragma unroll
        for (int j = 0; j < 54; j++) {
            float v = red[j];
            #pragma unroll
            for (int o = 16; o; o >>= 1) v += __shfl_xor_sync(0xffffffffu, v, o);
            if (lane == (j & 31)) wbuf[warp][j] = v;
        }
    }
    __syncthreads();

    // layout: [0..80]=S_lp (d*9+e), [81..125]=S_pp tri, [126..134]=s_pr,
    //         [135..179]=S_ll tri, [180..188]=s_la
    if (tid < 189) {
        int g, lj;
        if      (tid < 81)  { g = tid / 27; lj = tid - g*27; }
        else if (tid < 135) { g = 3; lj = tid - 81; }
        else                { g = 4; lj = tid - 135; }
        float s = wbuf[2*g][lj] + wbuf[2*g+1][lj];
        g_mpart[(nc*BD2 + band)*MSZ + tid] = s;
    }
}

// ============ k_rmi: one block per (n,c), fully-unrolled register Cholesky ==
__global__ __launch_bounds__(32) void k_rmi()
{
    __shared__ float m[192];
    const int nc = blockIdx.x;
    const int tid = threadIdx.x;

    for (int j = tid; j < 189; j += 32) {
        float s = 0.f;
        #pragma unroll
        for (int b = 0; b < BD2; b++) s += g_mpart[(nc*BD2 + b)*MSZ + j];
        m[j] = s;
    }
    __syncwarp();
    if (tid != 0) return;

    const float invL = 1.0f / (float)LLN;
    float spr[9], sla[9];
    #pragma unroll
    for (int d = 0; d < 9; d++) { spr[d] = m[126+d]; sla[d] = m[180+d]; }

    // ---- Cpp assemble + Cholesky (all indices compile-time) ----
    float cpp[45];
    {
        int k = 0;
        #pragma unroll
        for (int d = 0; d < 9; d++)
            #pragma unroll
            for (int e = d; e < 9; e++) {
                cpp[k] = m[81+k] - spr[d]*spr[e]*invL + (d==e ? ALPHA : 0.0f);
                k++;
            }
    }
    #pragma unroll
    for (int j = 0; j < 9; j++) {
        float s = cpp[TRI(j,j)];
        #pragma unroll
        for (int q = 0; q < j; q++) { float g = cpp[TRI(q,j)]; s -= g*g; }
        float gjj = sqrtf(fmaxf(s, 1e-20f));
        cpp[TRI(j,j)] = gjj;
        float inv = 1.0f / gjj;
        #pragma unroll
        for (int i = j+1; i < 9; i++) {
            float t = cpp[TRI(j,i)];
            #pragma unroll
            for (int q = 0; q < j; q++) t -= cpp[TRI(q,i)]*cpp[TRI(q,j)];
            cpp[TRI(j,i)] = t*inv;
        }
    }

    // ---- Clp assemble + forward solve Y = G^{-1} Clp^T ----
    float clp[81];
    #pragma unroll
    for (int d = 0; d < 9; d++)
        #pragma unroll
        for (int e = 0; e < 9; e++)
            clp[d*9+e] = m[d*9+e] - sla[d]*spr[e]*invL;

    #pragma unroll
    for (int d = 0; d < 9; d++)
        #pragma unroll
        for (int i = 0; i < 9; i++) {
            float s = clp[d*9+i];
            #pragma unroll
            for (int q = 0; q < i; q++) s -= cpp[TRI(q,i)]*clp[d*9+q];
            clp[d*9+i] = s / cpp[TRI(i,i)];
        }

    // ---- Cll assemble + Schur complement ----
    float cll[45];
    {
        int k = 0;
        #pragma unroll
        for (int d = 0; d < 9; d++)
            #pragma unroll
            for (int e = d; e < 9; e++) {
                float s = m[135+k] - sla[d]*sla[e]*invL;
                #pragma unroll
                for (int i = 0; i < 9; i++) s -= clp[d*9+i]*clp[e*9+i];
                if (d == e) s += ALPHA;
                cll[k] = s; k++;
            }
    }

    // ---- Cholesky of M + sum log diag ----
    float rmi = 0.0f;
    #pragma unroll
    for (int j = 0; j < 9; j++) {
        float s = cll[TRI(j,j)];
        #pragma unroll
        for (int q = 0; q < j; q++) { float g = cll[TRI(q,j)]; s -= g*g; }
        float gjj = sqrtf(fmaxf(s, 0.0f));
        cll[TRI(j,j)] = gjj;
        float inv = 1.0f / gjj;
        #pragma unroll
        for (int i = j+1; i < 9; i++) {
            float t = cll[TRI(j,i)];
            #pragma unroll
            for (int q = 0; q < j; q++) t -= cll[TRI(q,i)]*cll[TRI(q,j)];
            cll[TRI(j,i)] = t*inv;
        }
        rmi += logf(gjj + 1e-8f);
    }
    g_rmi[nc] = rmi;
}

// ============ k_fin2: CE reduce + sum rmi + final scalar ===================
__global__ __launch_bounds__(128) void k_fin2(float* __restrict__ out, int out_size)
{
    __shared__ float rce[128];
    __shared__ int   rcn[128];
    const int tid = threadIdx.x;

    float cs = 0.f; int cc = 0;
    for (int i = tid; i < NB*PH; i += 128) { cs += g_ce[i]; cc += g_cnt[i]; }
    rce[tid] = cs; rcn[tid] = cc;
    __syncthreads();
    for (int o = 64; o; o >>= 1) {
        if (tid < o) { rce[tid] += rce[tid+o]; rcn[tid] += rcn[tid+o]; }
        __syncthreads();
    }

    if (tid == 0) {
        float rs = 0.f;
        #pragma unroll
        for (int i = 0; i < NCCH; i++) rs += g_rmi[i];
        float normal = rce[0] / (float)rcn[0];
        float loss = 0.5f*normal + 0.5f*(rs / 36.0f);
        for (int i = 0; i < out_size; i++) out[i] = loss;
    }
}

extern "C" void kernel_launch(void* const* d_in, const int* in_sizes, int n_in,
                              void* d_out, int out_size)
{
    const float* score;
    const int*   tg;
    if (in_sizes[0] >= in_sizes[1]) { score = (const float*)d_in[0]; tg = (const int*)d_in[1]; }
    else                            { score = (const float*)d_in[1]; tg = (const int*)d_in[0]; }

    k_fused<<<dim3(PH, NB), 512>>>(score, tg);
    k_mom<<<dim3(NCCH, BD2), 320>>>();
    k_rmi<<<NCCH, 32>>>();
    k_fin2<<<1, 128>>>((float*)d_out, out_size);
}

// round 17
// speedup vs baseline: 3.8223x; 1.0490x over previous
#include <cuda_runtime.h>

#define NB 4
#define NC 21
#define HH 512
#define WW 512
#define PH 171
#define OH 169
#define NCCH 84
#define PP (PH*PH)
#define LLN (OH*OH)
#define SRW 176
#define RB 27
#define BD2 7
#define MSZ 192
#define ALPHA 5e-4f

__device__ float    g_pr[NCCH*PP];      // pooled clipped sigmoid − 0.5
__device__ unsigned g_lab[NB*PP];
__device__ float    g_mpart[NCCH*BD2*MSZ];
__device__ float    g_rmi[NCCH];
__device__ float    g_ce[NB*PH];
__device__ int      g_cnt[NB*PH];

__device__ __forceinline__ float ftanh(float x){float r;asm("tanh.approx.f32 %0,%1;":"=f"(r):"f"(x));return r;}

// ============ K1: CE + raw-score maxpool + sigmoid-after-pool + label bits ==
__global__ __launch_bounds__(512) void k_fused(const float* __restrict__ score,
                                               const int*   __restrict__ tg)
{
    __shared__ float    spx[NC*WW];
    __shared__ unsigned slab[WW];
    __shared__ float wce[16];
    __shared__ int   wcnt[16];
    __shared__ int   s_is64;

    const int oy = blockIdx.x, n = blockIdx.y, x = threadIdx.x;

    if (x == 0) {
        int is64 = 1;
        #pragma unroll
        for (int i = 0; i < 32; i++) if (tg[2*i+1] != 0) is64 = 0;
        s_is64 = is64;
    }
    __syncthreads();
    const bool is64 = (s_is64 != 0);
    const long long* tg64 = (const long long*)tg;

    float vpool[NC];
    #pragma unroll
    for (int cc = 0; cc < NC; cc++) vpool[cc] = -1e30f;
    unsigned labbits = 0;
    float ce = 0.0f; int cnt = 0;

    const int r0 = 3*oy - 1;
    #pragma unroll
    for (int k = 0; k < 3; k++) {
        int r = r0 + k;
        if (r < 0 || r >= HH) continue;
        int pix = (n*HH + r)*WW + x;
        int t = is64 ? (int)tg64[pix] : tg[pix];
        bool mask21 = (t >= 0 && t < NC);
        bool valid  = (t != 255);
        const float* bp = score + ((size_t)(n*NC)*HH + r)*WW + x;

        float s0 = 0.f, s1 = 0.f, s2 = 0.f, xt = 0.f;
        #pragma unroll
        for (int cc = 0; cc < NC; cc++) {
            float v = __ldg(bp + (size_t)cc*(HH*WW));
            float e = __expf(v);
            if (cc % 3 == 0) s0 += e; else if (cc % 3 == 1) s1 += e; else s2 += e;
            if (cc == t) xt = v;
            float vm = mask21 ? v : -1e30f;
            vpool[cc] = fmaxf(vpool[cc], vm);
        }
        if (valid) { ce += __logf((s0 + s1) + s2) - xt; cnt++; }
        if (mask21) labbits |= (1u << t);
    }

    #pragma unroll
    for (int cc = 0; cc < NC; cc++) spx[cc*WW + x] = vpool[cc];
    slab[x] = labbits;

    #pragma unroll
    for (int o = 16; o; o >>= 1) {
        ce  += __shfl_xor_sync(0xffffffffu, ce, o);
        cnt += __shfl_xor_sync(0xffffffffu, cnt, o);
    }
    if ((x & 31) == 0) { wce[x >> 5] = ce; wcnt[x >> 5] = cnt; }
    __syncthreads();
    if (x == 0) {
        float s = 0.f; int cc2 = 0;
        #pragma unroll
        for (int i = 0; i < 16; i++) { s += wce[i]; cc2 += wcnt[i]; }
        g_ce[n*PH + oy] = s; g_cnt[n*PH + oy] = cc2;
    }

    for (int idx = x; idx < NC*PH; idx += 512) {
        int c = idx / PH, ox = idx - c*PH;
        int c0 = 3*ox - 1;
        float pm = -1e30f; unsigned ob = 0;
        #pragma unroll
        for (int j = 0; j < 3; j++) {
            int cc = c0 + j;
            if (cc >= 0 && cc < WW) { pm = fmaxf(pm, spx[c*WW + cc]); ob |= slab[cc]; }
        }
        float sg  = fmaf(ftanh(0.5f*pm), 0.5f, 0.5f);
        float val = fminf(fmaxf(sg, 1e-6f), 1.0f) - 0.5f;
        g_pr[((n*NC + c)*PH + oy)*PH + ox] = val;
        if (c == 0) g_lab[(n*PH + oy)*PH + ox] = ob;
    }
}

// ============ K2: Gram moments, 5 groups x 64 thr, scalar FFMA =============
#define TRI(d,e) ((d)*9 - (d)*((d)-1)/2 + (e)-(d))

__device__ __forceinline__ void load8(const float* p, float* a)
{
    float4 u0 = *(const float4*)p;
    float4 u1 = *(const float4*)(p + 4);
    a[0]=u0.x; a[1]=u0.y; a[2]=u0.z; a[3]=u0.w;
    a[4]=u1.x; a[5]=u1.y; a[6]=u1.z; a[7]=u1.w;
}

__global__ __launch_bounds__(320, 2) void k_mom()
{
    __shared__ float sp[29*SRW];
    __shared__ float sl[29*SRW];
    __shared__ float wbuf[10][54];

    const int nc = blockIdx.x, band = blockIdx.y;
    const int n = nc / NC, c = nc - n*NC;
    const int tid = threadIdx.x;
    const int r0 = band*RB;
    const int rows_out = min(RB, OH - r0);
    const int nin = rows_out + 2;

    for (int i = tid; i < 29*SRW; i += 320) {
        int r = i / SRW, x = i - r*SRW;
        float pv = 0.f, lv = 0.f;
        if (r < nin && x < PH) {
            int gi = (r0 + r)*PH + x;
            pv = g_pr[nc*PP + gi];
            lv = ((g_lab[n*PP + gi] >> c) & 1u) ? 0.5f : -0.5f;
        }
        sp[i] = pv; sl[i] = lv;
    }
    __syncthreads();

    const int grp = tid >> 6;         // 0,1,2 = lp dy; 3 = pp; 4 = ll
    const int gt  = tid & 63;
    const int warp = tid >> 5, lane = tid & 31;
    const int nq = rows_out*43;

    if (grp < 3) {
        const int dy = grp;
        float acc[27];
        #pragma unroll
        for (int i = 0; i < 27; i++) acc[i] = 0.f;

        int row = (gt >= 43) ? 1 : 0;
        int qx  = gt - (row ? 43 : 0);
        for (int q = gt; q < nq; q += 64) {
            const int xq = qx*4;
            float A[8], B[3][8];
            load8(sl + (row+dy)*SRW + xq, A);
            #pragma unroll
            for (int ey = 0; ey < 3; ey++) load8(sp + (row+ey)*SRW + xq, B[ey]);
            const int nv = 169 - xq;
            #pragma unroll
            for (int q2 = 0; q2 < 4; q2++) {
                if (q2 < nv) {
                    #pragma unroll
                    for (int dx = 0; dx < 3; dx++) {
                        float l = A[q2+dx];
                        #pragma unroll
                        for (int e = 0; e < 9; e++)
                            acc[dx*9+e] = fmaf(l, B[e/3][q2 + e%3], acc[dx*9+e]);
                    }
                }
            }
            qx += 21; row += 1;
            if (qx >= 43) { qx -= 43; row += 1; }
        }
        #pragma unroll
        for (int j = 0; j < 27; j++) {
            float v = acc[j];
            #pragma unroll
            for (int o = 16; o; o >>= 1) v += __shfl_xor_sync(0xffffffffu, v, o);
            if (lane == (j & 31)) wbuf[warp][j] = v;
        }
    } else {
        const float* S = (grp == 3) ? sp : sl;
        float accT[45], accS[9];
        #pragma unroll
        for (int i = 0; i < 45; i++) accT[i] = 0.f;
        #pragma unroll
        for (int i = 0; i < 9; i++) accS[i] = 0.f;

        int row = (gt >= 43) ? 1 : 0;
        int qx  = gt - (row ? 43 : 0);
        for (int q = gt; q < nq; q += 64) {
            const int xq = qx*4;
            float B[3][8];
            #pragma unroll
            for (int y = 0; y < 3; y++) load8(S + (row+y)*SRW + xq, B[y]);
            const int nv = 169 - xq;
            #pragma unroll
            for (int q2 = 0; q2 < 4; q2++) {
                if (q2 < nv) {
                    float v[9];
                    #pragma unroll
                    for (int d = 0; d < 9; d++) v[d] = B[d/3][q2 + d%3];
                    int k = 0;
                    #pragma unroll
                    for (int d = 0; d < 9; d++) {
                        accS[d] += v[d];
                        #pragma unroll
                        for (int e = d; e < 9; e++) { accT[k] = fmaf(v[d], v[e], accT[k]); k++; }
                    }
                }
            }
            qx += 21; row += 1;
            if (qx >= 43) { qx -= 43; row += 1; }
        }
        float red[54];
        #pragma unroll
        for (int k = 0; k < 45; k++) red[k] = accT[k];
        #pragma unroll
        for (int d = 0; d < 9; d++) red[45+d] = accS[d];
        #pragma unroll
        for (int j = 0; j < 54; j++) {
            float v = red[j];
            #pragma unroll
            for (int o = 16; o; o >>= 1) v += __shfl_xor_sync(0xffffffffu, v, o);
            if (lane == (j & 31)) wbuf[warp][j] = v;
        }
    }
    __syncthreads();

    // layout: [0..80]=S_lp (d*9+e), [81..125]=S_pp tri, [126..134]=s_pr,
    //         [135..179]=S_ll tri, [180..188]=s_la
    if (tid < 189) {
        int g, lj;
        if      (tid < 81)  { g = tid / 27; lj = tid - g*27; }
        else if (tid < 135) { g = 3; lj = tid - 81; }
        else                { g = 4; lj = tid - 135; }
        float s = wbuf[2*g][lj] + wbuf[2*g+1][lj];
        g_mpart[(nc*BD2 + band)*MSZ + tid] = s;
    }
}

// ============ k_rmi: one block per (n,c), fully-unrolled register Cholesky ==
__global__ __launch_bounds__(32) void k_rmi()
{
    __shared__ float m[192];
    const int nc = blockIdx.x;
    const int tid = threadIdx.x;

    for (int j = tid; j < 189; j += 32) {
        float s = 0.f;
        #pragma unroll
        for (int b = 0; b < BD2; b++) s += g_mpart[(nc*BD2 + b)*MSZ + j];
        m[j] = s;
    }
    __syncwarp();
    if (tid != 0) return;

    const float invL = 1.0f / (float)LLN;
    float spr[9], sla[9];
    #pragma unroll
    for (int d = 0; d < 9; d++) { spr[d] = m[126+d]; sla[d] = m[180+d]; }

    // ---- Cpp assemble + Cholesky (all indices compile-time) ----
    float cpp[45];
    {
        int k = 0;
        #pragma unroll
        for (int d = 0; d < 9; d++)
            #pragma unroll
            for (int e = d; e < 9; e++) {
                cpp[k] = m[81+k] - spr[d]*spr[e]*invL + (d==e ? ALPHA : 0.0f);
                k++;
            }
    }
    #pragma unroll
    for (int j = 0; j < 9; j++) {
        float s = cpp[TRI(j,j)];
        #pragma unroll
        for (int q = 0; q < j; q++) { float g = cpp[TRI(q,j)]; s -= g*g; }
        float gjj = sqrtf(fmaxf(s, 1e-20f));
        cpp[TRI(j,j)] = gjj;
        float inv = 1.0f / gjj;
        #pragma unroll
        for (int i = j+1; i < 9; i++) {
            float t = cpp[TRI(j,i)];
            #pragma unroll
            for (int q = 0; q < j; q++) t -= cpp[TRI(q,i)]*cpp[TRI(q,j)];
            cpp[TRI(j,i)] = t*inv;
        }
    }

    // ---- Clp assemble + forward solve Y = G^{-1} Clp^T ----
    float clp[81];
    #pragma unroll
    for (int d = 0; d < 9; d++)
        #pragma unroll
        for (int e = 0; e < 9; e++)
            clp[d*9+e] = m[d*9+e] - sla[d]*spr[e]*invL;

    #pragma unroll
    for (int d = 0; d < 9; d++)
        #pragma unroll
        for (int i = 0; i < 9; i++) {
            float s = clp[d*9+i];
            #pragma unroll
            for (int q = 0; q < i; q++) s -= cpp[TRI(q,i)]*clp[d*9+q];
            clp[d*9+i] = s / cpp[TRI(i,i)];
        }

    // ---- Cll assemble + Schur complement ----
    float cll[45];
    {
        int k = 0;
        #pragma unroll
        for (int d = 0; d < 9; d++)
            #pragma unroll
            for (int e = d; e < 9; e++) {
                float s = m[135+k] - sla[d]*sla[e]*invL;
                #pragma unroll
                for (int i = 0; i < 9; i++) s -= clp[d*9+i]*clp[e*9+i];
                if (d == e) s += ALPHA;
                cll[k] = s; k++;
            }
    }

    // ---- Cholesky of M + sum log diag ----
    float rmi = 0.0f;
    #pragma unroll
    for (int j = 0; j < 9; j++) {
        float s = cll[TRI(j,j)];
        #pragma unroll
        for (int q = 0; q < j; q++) { float g = cll[TRI(q,j)]; s -= g*g; }
        float gjj = sqrtf(fmaxf(s, 0.0f));
        cll[TRI(j,j)] = gjj;
        float inv = 1.0f / gjj;
        #pragma unroll
        for (int i = j+1; i < 9; i++) {
            float t = cll[TRI(j,i)];
            #pragma unroll
            for (int q = 0; q < j; q++) t -= cll[TRI(q,i)]*cll[TRI(q,j)];
            cll[TRI(j,i)] = t*inv;
        }
        rmi += logf(gjj + 1e-8f);
    }
    g_rmi[nc] = rmi;
}

// ============ k_fin2: CE reduce + sum rmi + final scalar ===================
__global__ __launch_bounds__(128) void k_fin2(float* __restrict__ out, int out_size)
{
    __shared__ float rce[128];
    __shared__ int   rcn[128];
    const int tid = threadIdx.x;

    float cs = 0.f; int cc = 0;
    for (int i = tid; i < NB*PH; i += 128) { cs += g_ce[i]; cc += g_cnt[i]; }
    rce[tid] = cs; rcn[tid] = cc;
    __syncthreads();
    for (int o = 64; o; o >>= 1) {
        if (tid < o) { rce[tid] += rce[tid+o]; rcn[tid] += rcn[tid+o]; }
        __syncthreads();
    }

    if (tid == 0) {
        float rs = 0.f;
        #pragma unroll
        for (int i = 0; i < NCCH; i++) rs += g_rmi[i];
        float normal = rce[0] / (float)rcn[0];
        float loss = 0.5f*normal + 0.5f*(rs / 36.0f);
        for (int i = 0; i < out_size; i++) out[i] = loss;
    }
}

extern "C" void kernel_launch(void* const* d_in, const int* in_sizes, int n_in,
                              void* d_out, int out_size)
{
    const float* score;
    const int*   tg;
    if (in_sizes[0] >= in_sizes[1]) { score = (const float*)d_in[0]; tg = (const int*)d_in[1]; }
    else                            { score = (const float*)d_in[1]; tg = (const int*)d_in[0]; }

    k_fused<<<dim3(PH, NB), 512>>>(score, tg);
    k_mom<<<dim3(NCCH, BD2), 320>>>();
    k_rmi<<<NCCH, 32>>>();
    k_fin2<<<1, 128>>>((float*)d_out, out_size);
}